// round 14
// baseline (speedup 1.0000x reference)
#include <cuda_runtime.h>
#include <cuda_bf16.h>
#include <cuda_fp16.h>
#include <cstdint>
#include <cstddef>

// ============================================================================
// AutoregressiveGRU on GB300 — sm_103 base target, HMMA mma.sync m16n8k16.
//
// fp16 2-term scheme: acc += Ah*Bh ; acc2 += Ah*(Bl*2048); res = acc+acc2/2048.
// One fused GEMM [256,1024]x[1024,4096] per step (z|r|xh|uh packed per d).
//
// R14 vs R13 (barrier cost ~1.8us/step by L2-atom model):
//  - per-ctam sync groups: 4 independent 32-CTA barriers (256B-padded ctrs)
//    (consumer of row-block ctam depends only on same-ctam producers)
//  - epilogue reordered: h16_out -> arrive -> out/hstate stores -> wait
// ============================================================================

#define DD 1024
#define BATCH 256
#define TSTEPS 128
#define NPACK 4096

#define CTA_M 64
#define CTA_N 128
#define KC 64            // K per chunk (64 fp16 = 128 B/row)
#define KCH 16           // 1024 / 64
#define STAGES 4
#define A_TILE_B (CTA_M * 128)            // 8192
#define B_TILE_B (CTA_N * 128)            // 16384
#define STAGE_BYTES (A_TILE_B + 2 * B_TILE_B)       // 40960
#define ES_BYTES (CTA_M * CTA_N * 4)                // 32768 epilogue scratch
#define SMEM_DYN (STAGES * STAGE_BYTES + ES_BYTES)  // 196608

// ---------------- device globals --------------------------------------------
__device__ __half g_Wmh[NPACK * DD];     // main weights hi
__device__ __half g_Wml[NPACK * DD];     // main weights (lo * 2048)
__device__ __half g_W1h[NPACK * DD];     // step-1 weights hi
__device__ __half g_W1l[NPACK * DD];     // step-1 weights (lo * 2048)
__device__ __half g_h16[2][BATCH * DD];  // fp16 state ping-pong
__device__ float g_hstate[BATCH * DD];   // fp32 state
__device__ float g_bias[NPACK];
struct BarSlot { unsigned v; unsigned pad[63]; };   // 256B apart
__device__ BarSlot g_bar4[4];            // per-ctam barrier counters

// ---------------- PTX helpers -----------------------------------------------
__device__ __forceinline__ uint32_t smem_u32(const void* p) {
    uint32_t a;
    asm("{ .reg .u64 t; cvta.to.shared.u64 t, %1; cvt.u32.u64 %0, t; }" : "=r"(a) : "l"(p));
    return a;
}
__device__ __forceinline__ void cp16(uint32_t dst, const void* src) {
    asm volatile("cp.async.cg.shared.global [%0], [%1], 16;" :: "r"(dst), "l"(src) : "memory");
}
__device__ __forceinline__ void cp_commit() {
    asm volatile("cp.async.commit_group;" ::: "memory");
}
template <int N>
__device__ __forceinline__ void cp_wait() {
    asm volatile("cp.async.wait_group %0;" :: "n"(N) : "memory");
}
__device__ __forceinline__ void ldsm_x4(uint32_t* r, uint32_t addr) {
    asm volatile("ldmatrix.sync.aligned.m8n8.x4.shared.b16 {%0,%1,%2,%3}, [%4];"
                 : "=r"(r[0]), "=r"(r[1]), "=r"(r[2]), "=r"(r[3]) : "r"(addr));
}
__device__ __forceinline__ void mma_f16(float* c, const uint32_t* a, uint32_t b0, uint32_t b1) {
    asm volatile("mma.sync.aligned.m16n8k16.row.col.f32.f16.f16.f32 "
                 "{%0,%1,%2,%3}, {%4,%5,%6,%7}, {%8,%9}, {%0,%1,%2,%3};"
                 : "+f"(c[0]), "+f"(c[1]), "+f"(c[2]), "+f"(c[3])
                 : "r"(a[0]), "r"(a[1]), "r"(a[2]), "r"(a[3]), "r"(b0), "r"(b1));
}

// ---------------- persistent kernel ------------------------------------------
__global__ __launch_bounds__(512, 1) void gru_persistent_kernel(
    const __half* __restrict__ Wmh, const __half* __restrict__ Wml,
    const __half* __restrict__ W1h, const __half* __restrict__ W1l,
    __half* __restrict__ h16,            // [2][BATCH*DD]
    float* __restrict__ hstate,
    const float* __restrict__ bias, float* __restrict__ out)
{
    extern __shared__ __align__(128) char smem_raw[];
    const uint32_t sbase = smem_u32(smem_raw);
    float* es = (float*)(smem_raw + STAGES * STAGE_BYTES);
    const int tid = threadIdx.x;
    const int wid = tid >> 5, lane = tid & 31;
    const int ctan = blockIdx.x;   // 0..31
    const int ctam = blockIdx.y;   // 0..3

    const int wm = wid & 1;        // 0..1 : 32-row warp block
    const int wn = wid >> 1;       // 0..7 : 16-col warp block

    // per-thread cp.async coords
    const int cprowA = tid >> 3, cpgrpA = tid & 7;
    const uint32_t cpswA = (uint32_t)(cprowA * 128) + (uint32_t)((cpgrpA ^ (cprowA & 7)) << 4);

    auto issue_A = [&](int slot, int k0, const __half* Ag) {
        cp16(sbase + (uint32_t)slot * STAGE_BYTES + cpswA,
             Ag + (size_t)cprowA * DD + k0 + cpgrpA * 8);
    };
    auto issue_Bh = [&](int slot, int k0, const __half* Bhg) {
        uint32_t tb = sbase + (uint32_t)slot * STAGE_BYTES + A_TILE_B;
#pragma unroll
        for (int it = 0; it < 2; ++it) {
            int idx = tid + it * 512;
            int row = idx >> 3, grp = idx & 7;
            uint32_t sw = (uint32_t)(row * 128) + (uint32_t)((grp ^ (row & 7)) << 4);
            cp16(tb + sw, Bhg + (size_t)row * DD + k0 + grp * 8);
        }
    };
    auto issue_Bl = [&](int slot, int k0, const __half* Blg) {
        uint32_t tb = sbase + (uint32_t)slot * STAGE_BYTES + A_TILE_B + B_TILE_B;
#pragma unroll
        for (int it = 0; it < 2; ++it) {
            int idx = tid + it * 512;
            int row = idx >> 3, grp = idx & 7;
            uint32_t sw = (uint32_t)(row * 128) + (uint32_t)((grp ^ (row & 7)) << 4);
            cp16(tb + sw, Blg + (size_t)row * DD + k0 + grp * 8);
        }
    };

    // fragment addressing
    const int arow = wm * 32 + (lane & 15);
    const int agl = (lane >> 4);
    const int brow = wn * 16 + (lane & 7) + ((lane >> 4) & 1) * 8;
    const int bgl = (lane >> 3) & 1;

    uint32_t fa[2][2][4], fbh[2][4], fbl[2][4];

#define LDSM_A(b, mt, kk_) do {                                                      \
    int row_ = arow + (mt) * 16;                                                     \
    uint32_t off_ = (uint32_t)(row_ * 128) +                                         \
                    (uint32_t)(((((kk_) * 2) + agl) ^ (row_ & 7)) << 4);             \
    ldsm_x4(fa[b][mt], aB + off_);                                                   \
} while (0)
#define LDSM_BH(b, kk_) do {                                                         \
    uint32_t off_ = (uint32_t)(brow * 128) +                                         \
                    (uint32_t)(((((kk_) * 2) + bgl) ^ (brow & 7)) << 4);             \
    ldsm_x4(fbh[b], bhB + off_);                                                     \
} while (0)
#define LDSM_BL(b, kk_) do {                                                         \
    uint32_t off_ = (uint32_t)(brow * 128) +                                         \
                    (uint32_t)(((((kk_) * 2) + bgl) ^ (brow & 7)) << 4);             \
    ldsm_x4(fbl[b], blB + off_);                                                     \
} while (0)
#define KK_BODY(bc, bn, kkn, do_ld) do {                                             \
    if (do_ld) LDSM_A(bn, 0, kkn);                                                   \
    mma_f16(acc[0][0],  fa[bc][0], fbh[bc][0], fbh[bc][1]);                          \
    mma_f16(acc[0][1],  fa[bc][0], fbh[bc][2], fbh[bc][3]);                          \
    if (do_ld) LDSM_BH(bn, kkn);                                                     \
    mma_f16(acc2[0][0], fa[bc][0], fbl[bc][0], fbl[bc][1]);                          \
    mma_f16(acc2[0][1], fa[bc][0], fbl[bc][2], fbl[bc][3]);                          \
    if (do_ld) LDSM_A(bn, 1, kkn);                                                   \
    mma_f16(acc[1][0],  fa[bc][1], fbh[bc][0], fbh[bc][1]);                          \
    mma_f16(acc[1][1],  fa[bc][1], fbh[bc][2], fbh[bc][3]);                          \
    if (do_ld) LDSM_BL(bn, kkn);                                                     \
    mma_f16(acc2[1][0], fa[bc][1], fbl[bc][0], fbl[bc][1]);                          \
    mma_f16(acc2[1][1], fa[bc][1], fbl[bc][2], fbl[bc][3]);                          \
} while (0)

    // ---- one-time prologue (t=0): B chunks 0..2 (W1), then A chunks 0..2 ----
    {
        const __half* Bhg0 = W1h + (size_t)ctan * CTA_N * DD;
        const __half* Blg0 = W1l + (size_t)ctan * CTA_N * DD;
        const __half* Ag0 = h16 + (size_t)ctam * CTA_M * DD;   // buffer 0
#pragma unroll
        for (int c = 0; c < 3; ++c) {
            issue_Bh(c, c * KC, Bhg0); issue_Bl(c, c * KC, Blg0); cp_commit();
        }
#pragma unroll
        for (int c = 0; c < 3; ++c) { issue_A(c, c * KC, Ag0); cp_commit(); }
    }

    const __half* BhgN = Wmh + (size_t)ctan * CTA_N * DD;   // steps >= 1
    const __half* BlgN = Wml + (size_t)ctan * CTA_N * DD;
    volatile unsigned* mybar = &g_bar4[ctam].v;

    for (int t = 0; t < TSTEPS; ++t) {
        const int bin = t & 1, bout = bin ^ 1;
        const __half* Ag = h16 + (size_t)bin * (BATCH * DD) + (size_t)ctam * CTA_M * DD;
        const __half* Bhg = (t == 0) ? (W1h + (size_t)ctan * CTA_N * DD) : BhgN;
        const __half* Blg = (t == 0) ? (W1l + (size_t)ctan * CTA_N * DD) : BlgN;
        const bool have_next = (t + 1 < TSTEPS);

        float acc[2][2][4], acc2[2][2][4];
#pragma unroll
        for (int i = 0; i < 2; ++i)
#pragma unroll
            for (int j = 0; j < 2; ++j)
#pragma unroll
                for (int k = 0; k < 4; ++k) { acc[i][j][k] = 0.0f; acc2[i][j][k] = 0.0f; }

        for (int i = 0; i < KCH; ++i) {
            cp_wait<2>();
            __syncthreads();
            uint32_t base = sbase + (uint32_t)(i & (STAGES - 1)) * STAGE_BYTES;
            const uint32_t aB = base;
            const uint32_t bhB = base + A_TILE_B, blB = bhB + B_TILE_B;

            const int pf = i + 3;
            int mode, pslot, pk0;
            if (pf < KCH) { mode = 0; pslot = pf & (STAGES - 1); pk0 = pf * KC; }
            else if (have_next && pf - KCH < 3) { mode = 1; pslot = pf - KCH; pk0 = (pf - KCH) * KC; }
            else { mode = 2; pslot = 0; pk0 = 0; }

            LDSM_A(0, 0, 0); LDSM_BH(0, 0); LDSM_A(0, 1, 0); LDSM_BL(0, 0);

            KK_BODY(0, 1, 1, true);
            if (mode == 0) issue_A(pslot, pk0, Ag);
            else if (mode == 1) issue_Bh(pslot, pk0, BhgN);
            KK_BODY(1, 0, 2, true);
            if (mode == 0) issue_Bh(pslot, pk0, Bhg);
            else if (mode == 1) issue_Bl(pslot, pk0, BlgN);
            KK_BODY(0, 1, 3, true);
            if (mode == 0) issue_Bl(pslot, pk0, Blg);
            cp_commit();
            KK_BODY(1, 0, 0, false);
        }

        // ---- epilogue stage 1: acc -> smem ----
        {
            const float s = 1.0f / 2048.0f;
            const int r0 = wm * 32 + (lane >> 2);
            const int c0 = wn * 16 + (lane & 3) * 2;
#pragma unroll
            for (int mt = 0; mt < 2; ++mt)
#pragma unroll
                for (int nb = 0; nb < 2; ++nb) {
                    int r = r0 + mt * 16, c = c0 + nb * 8;
                    *(float2*)&es[r * 128 + c] =
                        make_float2(acc[mt][nb][0] + acc2[mt][nb][0] * s,
                                    acc[mt][nb][1] + acc2[mt][nb][1] * s);
                    *(float2*)&es[(r + 8) * 128 + c] =
                        make_float2(acc[mt][nb][2] + acc2[mt][nb][2] * s,
                                    acc[mt][nb][3] + acc2[mt][nb][3] * s);
                }
        }
        __syncthreads();

        // ---- epilogue stage 2: gates; write h16_out FIRST (peers wait on it) ----
        __half* h16_out = h16 + (size_t)bout * (BATCH * DD);
        float hn_reg[4];
        size_t hidx_reg[4];
#pragma unroll
        for (int p = 0; p < 4; ++p) {
            int linear = p * 512 + tid;              // 0..2047
            int m = linear >> 5;                     // 0..63
            int dloc = linear & 31;                  // 0..31
            float4 v = *(float4*)&es[m * 128 + dloc * 4];
            float4 bb = __ldg((const float4*)(bias + ctan * 128 + dloc * 4));
            float vz = v.x + bb.x;
            float vr = v.y + bb.y;
            float vh = v.z + bb.z;
            float vu = v.w + bb.w;
            float z = 1.0f / (1.0f + __expf(-vz));
            float r = 1.0f / (1.0f + __expf(-vr));
            float hh = tanhf(vh + r * vu);
            int gm = ctam * CTA_M + m;
            int d = ctan * 32 + dloc;
            size_t hidx = (size_t)gm * DD + d;
            float hold = hstate[hidx];
            float hn = z * hold + (1.0f - z) * hh;
            h16_out[hidx] = __float2half_rn(hn);
            hn_reg[p] = hn;
            hidx_reg[p] = hidx;
        }
        __syncthreads();

        // ---- arrive early (group barrier), then overlap out/hstate stores ----
        if (have_next) {
            if (tid == 0) { __threadfence(); atomicAdd((unsigned*)mybar, 1u); }
        }
#pragma unroll
        for (int p = 0; p < 4; ++p) {
            int linear = p * 512 + tid;
            int m = linear >> 5;
            int dloc = linear & 31;
            int gm = ctam * CTA_M + m;
            int d = ctan * 32 + dloc;
            out[(size_t)gm * (TSTEPS * DD) + (size_t)t * DD + d] = hn_reg[p];
            hstate[hidx_reg[p]] = hn_reg[p];
        }

        if (have_next) {
            // ---- wait for own ctam group (32 CTAs), then load A tiles ----
            if (tid == 0) {
                const unsigned target = 32u * (unsigned)(t + 1);
                while (*mybar < target) { }
                __threadfence();
            }
            __syncthreads();
            const __half* AgN = h16 + (size_t)bout * (BATCH * DD) + (size_t)ctam * CTA_M * DD;
#pragma unroll
            for (int c = 0; c < 3; ++c) { issue_A(c, c * KC, AgN); cp_commit(); }
        }
    }
#undef KK_BODY
#undef LDSM_A
#undef LDSM_BH
#undef LDSM_BL
}

// ---------------- pack / init kernels ---------------------------------------
__global__ void pack_weights(const float* __restrict__ W, const float* __restrict__ U,
                             const float* __restrict__ b,
                             __half* __restrict__ Wmh, __half* __restrict__ Wml,
                             __half* __restrict__ W1h, __half* __restrict__ W1l,
                             float* __restrict__ bp)
{
    int idx = blockIdx.x * blockDim.x + threadIdx.x;
    if (idx >= NPACK * DD) return;
    int c = idx >> 10;          // packed column (d*4 + gate)
    int k = idx & 1023;
    int d = c >> 2, g = c & 3;
    const int TD = 3 * DD;
    float vm, v1;
    if (g == 0)      { float u = U[(size_t)k * TD + d];            vm = W[(size_t)k * TD + d] + u;            v1 = u; }
    else if (g == 1) { float u = U[(size_t)k * TD + DD + d];       vm = W[(size_t)k * TD + DD + d] + u;       v1 = u; }
    else if (g == 2) { vm = W[(size_t)k * TD + 2 * DD + d];        v1 = 0.0f; }
    else             { float u = U[(size_t)k * TD + 2 * DD + d];   vm = u;    v1 = u; }
    __half h1 = __float2half_rn(vm);
    Wmh[idx] = h1;
    Wml[idx] = __float2half_rn((vm - __half2float(h1)) * 2048.0f);
    __half h2 = __float2half_rn(v1);
    W1h[idx] = h2;
    W1l[idx] = __float2half_rn((v1 - __half2float(h2)) * 2048.0f);
    if (k == 0)
        bp[c] = (g == 0) ? b[d] : (g == 1) ? b[DD + d] : (g == 2) ? b[2 * DD + d] : 0.0f;
}

__global__ void init_h(const float* __restrict__ x,
                       __half* __restrict__ h16, float* __restrict__ hstate)
{
    int i = blockIdx.x * blockDim.x + threadIdx.x;
    if (i < 4) g_bar4[i].v = 0u;   // reset group barriers every launch
    if (i < BATCH * DD) {
        float v = x[i];
        h16[i] = __float2half_rn(v);
        hstate[i] = v;
    }
}

// ---------------- launch -----------------------------------------------------
extern "C" void kernel_launch(void* const* d_in, const int* in_sizes, int n_in,
                              void* d_out, int out_size)
{
    const float* x = (const float*)d_in[0];
    const float* W = (const float*)d_in[1];
    const float* U = (const float*)d_in[2];
    const float* b = (const float*)d_in[3];
    float* out = (float*)d_out;

    void *pWmh, *pWml, *pW1h, *pW1l, *pH16, *pHst, *pBias;
    cudaGetSymbolAddress(&pWmh, g_Wmh);
    cudaGetSymbolAddress(&pWml, g_Wml);
    cudaGetSymbolAddress(&pW1h, g_W1h);
    cudaGetSymbolAddress(&pW1l, g_W1l);
    cudaGetSymbolAddress(&pH16, g_h16);
    cudaGetSymbolAddress(&pHst, g_hstate);
    cudaGetSymbolAddress(&pBias, g_bias);
    __half* Wmh = (__half*)pWmh;
    __half* Wml = (__half*)pWml;
    __half* W1h = (__half*)pW1h;
    __half* W1l = (__half*)pW1l;
    __half* H16 = (__half*)pH16;     // [2][BATCH*DD]
    float* Hst = (float*)pHst;
    float* Bias = (float*)pBias;

    cudaFuncSetAttribute(gru_persistent_kernel,
                         cudaFuncAttributeMaxDynamicSharedMemorySize, SMEM_DYN);

    pack_weights<<<(NPACK * DD + 255) / 256, 256>>>(W, U, b, Wmh, Wml, W1h, W1l, Bias);
    init_h<<<(BATCH * DD + 255) / 256, 256>>>(x, H16, Hst);

    dim3 grid(32, 4);   // 128 CTAs <= 148 SMs, 1 CTA/SM: all co-resident
    gru_persistent_kernel<<<grid, 512, SMEM_DYN>>>(
        Wmh, Wml, W1h, W1l, H16, Hst, Bias, out);
    (void)in_sizes; (void)n_in; (void)out_size;
}

// round 16
// speedup vs baseline: 1.0376x; 1.0376x over previous
#include <cuda_runtime.h>
#include <cuda_bf16.h>
#include <cuda_fp16.h>
#include <cstdint>
#include <cstddef>

// ============================================================================
// AutoregressiveGRU on GB300 — sm_103 base target, HMMA mma.sync m16n8k16.
//
// fp16 2-term scheme (FULL correction, every chunk — half-K correction
// measured 1.1e-3 and failed; the weight-residual term is a systematic
// error, not averageable noise):
//   acc  += fp16(h)*fp16(W) ;  acc2 += fp16(h)*(Wlo*2048)
//   res = acc + acc2/2048
// One fused GEMM [256,1024]x[1024,4096] per step (z|r|xh|uh packed per d).
//
// R16 = R13 arithmetic + fp32 state registerized (epilogue critical path
// loses a global-load; 2 MB/step hstate traffic removed).
// ============================================================================

#define DD 1024
#define BATCH 256
#define TSTEPS 128
#define NPACK 4096

#define CTA_M 64
#define CTA_N 128
#define KC 64            // K per chunk (64 fp16 = 128 B/row)
#define KCH 16           // 1024 / 64
#define STAGES 4
#define A_TILE_B (CTA_M * 128)            // 8192
#define B_TILE_B (CTA_N * 128)            // 16384
#define STAGE_BYTES (A_TILE_B + 2 * B_TILE_B)       // 40960
#define ES_BYTES (CTA_M * CTA_N * 4)                // 32768 epilogue scratch
#define SMEM_DYN (STAGES * STAGE_BYTES + ES_BYTES)  // 196608

// ---------------- device globals --------------------------------------------
__device__ __half g_Wmh[NPACK * DD];     // main weights hi
__device__ __half g_Wml[NPACK * DD];     // main weights (lo * 2048)
__device__ __half g_W1h[NPACK * DD];     // step-1 weights hi
__device__ __half g_W1l[NPACK * DD];     // step-1 weights (lo * 2048)
__device__ __half g_h16[2][BATCH * DD];  // fp16 state ping-pong
__device__ float g_bias[NPACK];
__device__ unsigned g_bar;               // grid barrier (reset by init_h)

// ---------------- PTX helpers -----------------------------------------------
__device__ __forceinline__ uint32_t smem_u32(const void* p) {
    uint32_t a;
    asm("{ .reg .u64 t; cvta.to.shared.u64 t, %1; cvt.u32.u64 %0, t; }" : "=r"(a) : "l"(p));
    return a;
}
__device__ __forceinline__ void cp16(uint32_t dst, const void* src) {
    asm volatile("cp.async.cg.shared.global [%0], [%1], 16;" :: "r"(dst), "l"(src) : "memory");
}
__device__ __forceinline__ void cp_commit() {
    asm volatile("cp.async.commit_group;" ::: "memory");
}
template <int N>
__device__ __forceinline__ void cp_wait() {
    asm volatile("cp.async.wait_group %0;" :: "n"(N) : "memory");
}
__device__ __forceinline__ void ldsm_x4(uint32_t* r, uint32_t addr) {
    asm volatile("ldmatrix.sync.aligned.m8n8.x4.shared.b16 {%0,%1,%2,%3}, [%4];"
                 : "=r"(r[0]), "=r"(r[1]), "=r"(r[2]), "=r"(r[3]) : "r"(addr));
}
__device__ __forceinline__ void mma_f16(float* c, const uint32_t* a, uint32_t b0, uint32_t b1) {
    asm volatile("mma.sync.aligned.m16n8k16.row.col.f32.f16.f16.f32 "
                 "{%0,%1,%2,%3}, {%4,%5,%6,%7}, {%8,%9}, {%0,%1,%2,%3};"
                 : "+f"(c[0]), "+f"(c[1]), "+f"(c[2]), "+f"(c[3])
                 : "r"(a[0]), "r"(a[1]), "r"(a[2]), "r"(a[3]), "r"(b0), "r"(b1));
}

// ---------------- persistent kernel ------------------------------------------
__global__ __launch_bounds__(512, 1) void gru_persistent_kernel(
    const __half* __restrict__ Wmh, const __half* __restrict__ Wml,
    const __half* __restrict__ W1h, const __half* __restrict__ W1l,
    __half* __restrict__ h16,            // [2][BATCH*DD]
    const float* __restrict__ x,
    const float* __restrict__ bias, float* __restrict__ out)
{
    extern __shared__ __align__(128) char smem_raw[];
    const uint32_t sbase = smem_u32(smem_raw);
    float* es = (float*)(smem_raw + STAGES * STAGE_BYTES);
    const int tid = threadIdx.x;
    const int wid = tid >> 5, lane = tid & 31;
    const int ctan = blockIdx.x;   // 0..31
    const int ctam = blockIdx.y;   // 0..3

    const int wm = wid & 1;        // 0..1 : 32-row warp block
    const int wn = wid >> 1;       // 0..7 : 16-col warp block

    // per-thread cp.async coords
    const int cprowA = tid >> 3, cpgrpA = tid & 7;
    const uint32_t cpswA = (uint32_t)(cprowA * 128) + (uint32_t)((cpgrpA ^ (cprowA & 7)) << 4);

    auto issue_A = [&](int slot, int k0, const __half* Ag) {
        cp16(sbase + (uint32_t)slot * STAGE_BYTES + cpswA,
             Ag + (size_t)cprowA * DD + k0 + cpgrpA * 8);
    };
    auto issue_Bh = [&](int slot, int k0, const __half* Bhg) {
        uint32_t tb = sbase + (uint32_t)slot * STAGE_BYTES + A_TILE_B;
#pragma unroll
        for (int it = 0; it < 2; ++it) {
            int idx = tid + it * 512;
            int row = idx >> 3, grp = idx & 7;
            uint32_t sw = (uint32_t)(row * 128) + (uint32_t)((grp ^ (row & 7)) << 4);
            cp16(tb + sw, Bhg + (size_t)row * DD + k0 + grp * 8);
        }
    };
    auto issue_Bl = [&](int slot, int k0, const __half* Blg) {
        uint32_t tb = sbase + (uint32_t)slot * STAGE_BYTES + A_TILE_B + B_TILE_B;
#pragma unroll
        for (int it = 0; it < 2; ++it) {
            int idx = tid + it * 512;
            int row = idx >> 3, grp = idx & 7;
            uint32_t sw = (uint32_t)(row * 128) + (uint32_t)((grp ^ (row & 7)) << 4);
            cp16(tb + sw, Blg + (size_t)row * DD + k0 + grp * 8);
        }
    };

    // fragment addressing
    const int arow = wm * 32 + (lane & 15);
    const int agl = (lane >> 4);
    const int brow = wn * 16 + (lane & 7) + ((lane >> 4) & 1) * 8;
    const int bgl = (lane >> 3) & 1;

    uint32_t fa[2][2][4], fbh[2][4], fbl[2][4];

#define LDSM_A(b, mt, kk_) do {                                                      \
    int row_ = arow + (mt) * 16;                                                     \
    uint32_t off_ = (uint32_t)(row_ * 128) +                                         \
                    (uint32_t)(((((kk_) * 2) + agl) ^ (row_ & 7)) << 4);             \
    ldsm_x4(fa[b][mt], aB + off_);                                                   \
} while (0)
#define LDSM_BH(b, kk_) do {                                                         \
    uint32_t off_ = (uint32_t)(brow * 128) +                                         \
                    (uint32_t)(((((kk_) * 2) + bgl) ^ (brow & 7)) << 4);             \
    ldsm_x4(fbh[b], bhB + off_);                                                     \
} while (0)
#define LDSM_BL(b, kk_) do {                                                         \
    uint32_t off_ = (uint32_t)(brow * 128) +                                         \
                    (uint32_t)(((((kk_) * 2) + bgl) ^ (brow & 7)) << 4);             \
    ldsm_x4(fbl[b], blB + off_);                                                     \
} while (0)
#define KK_BODY(bc, bn, kkn, do_ld) do {                                             \
    if (do_ld) LDSM_A(bn, 0, kkn);                                                   \
    mma_f16(acc[0][0],  fa[bc][0], fbh[bc][0], fbh[bc][1]);                          \
    mma_f16(acc[0][1],  fa[bc][0], fbh[bc][2], fbh[bc][3]);                          \
    if (do_ld) LDSM_BH(bn, kkn);                                                     \
    mma_f16(acc2[0][0], fa[bc][0], fbl[bc][0], fbl[bc][1]);                          \
    mma_f16(acc2[0][1], fa[bc][0], fbl[bc][2], fbl[bc][3]);                          \
    if (do_ld) LDSM_A(bn, 1, kkn);                                                   \
    mma_f16(acc[1][0],  fa[bc][1], fbh[bc][0], fbh[bc][1]);                          \
    mma_f16(acc[1][1],  fa[bc][1], fbh[bc][2], fbh[bc][3]);                          \
    if (do_ld) LDSM_BL(bn, kkn);                                                     \
    mma_f16(acc2[1][0], fa[bc][1], fbl[bc][0], fbl[bc][1]);                          \
    mma_f16(acc2[1][1], fa[bc][1], fbl[bc][2], fbl[bc][3]);                          \
} while (0)

    // ---- fp32 state in registers: thread owns the same (row,d) every step ----
    float hold_reg[4];
#pragma unroll
    for (int p = 0; p < 4; ++p) {
        int linear = p * 512 + tid;
        int m = linear >> 5, dloc = linear & 31;
        hold_reg[p] = x[(size_t)(ctam * CTA_M + m) * DD + ctan * 32 + dloc];
    }

    // ---- one-time prologue (t=0): B chunks 0..2 (W1), then A chunks 0..2 ----
    {
        const __half* Bhg0 = W1h + (size_t)ctan * CTA_N * DD;
        const __half* Blg0 = W1l + (size_t)ctan * CTA_N * DD;
        const __half* Ag0 = h16 + (size_t)ctam * CTA_M * DD;   // buffer 0
#pragma unroll
        for (int c = 0; c < 3; ++c) {
            issue_Bh(c, c * KC, Bhg0); issue_Bl(c, c * KC, Blg0); cp_commit();
        }
#pragma unroll
        for (int c = 0; c < 3; ++c) { issue_A(c, c * KC, Ag0); cp_commit(); }
    }

    const __half* BhgN = Wmh + (size_t)ctan * CTA_N * DD;   // steps >= 1
    const __half* BlgN = Wml + (size_t)ctan * CTA_N * DD;

    for (int t = 0; t < TSTEPS; ++t) {
        const int bin = t & 1, bout = bin ^ 1;
        const __half* Ag = h16 + (size_t)bin * (BATCH * DD) + (size_t)ctam * CTA_M * DD;
        const __half* Bhg = (t == 0) ? (W1h + (size_t)ctan * CTA_N * DD) : BhgN;
        const __half* Blg = (t == 0) ? (W1l + (size_t)ctan * CTA_N * DD) : BlgN;
        const bool have_next = (t + 1 < TSTEPS);

        float acc[2][2][4], acc2[2][2][4];
#pragma unroll
        for (int i = 0; i < 2; ++i)
#pragma unroll
            for (int j = 0; j < 2; ++j)
#pragma unroll
                for (int k = 0; k < 4; ++k) { acc[i][j][k] = 0.0f; acc2[i][j][k] = 0.0f; }

        for (int i = 0; i < KCH; ++i) {
            cp_wait<2>();
            __syncthreads();
            uint32_t base = sbase + (uint32_t)(i & (STAGES - 1)) * STAGE_BYTES;
            const uint32_t aB = base;
            const uint32_t bhB = base + A_TILE_B, blB = bhB + B_TILE_B;

            const int pf = i + 3;
            // mode 0: this step's chunk pf; mode 1: next step's B tile; mode 2: none
            int mode, pslot, pk0;
            if (pf < KCH) { mode = 0; pslot = pf & (STAGES - 1); pk0 = pf * KC; }
            else if (have_next && pf - KCH < 3) { mode = 1; pslot = pf - KCH; pk0 = (pf - KCH) * KC; }
            else { mode = 2; pslot = 0; pk0 = 0; }

            LDSM_A(0, 0, 0); LDSM_BH(0, 0); LDSM_A(0, 1, 0); LDSM_BL(0, 0);

            KK_BODY(0, 1, 1, true);
            if (mode == 0) issue_A(pslot, pk0, Ag);
            else if (mode == 1) issue_Bh(pslot, pk0, BhgN);
            KK_BODY(1, 0, 2, true);
            if (mode == 0) issue_Bh(pslot, pk0, Bhg);
            else if (mode == 1) issue_Bl(pslot, pk0, BlgN);
            KK_BODY(0, 1, 3, true);
            if (mode == 0) issue_Bl(pslot, pk0, Blg);
            cp_commit();
            KK_BODY(1, 0, 0, false);
        }

        // ---- epilogue stage 1: acc -> smem ----
        {
            const float s = 1.0f / 2048.0f;
            const int r0 = wm * 32 + (lane >> 2);
            const int c0 = wn * 16 + (lane & 3) * 2;
#pragma unroll
            for (int mt = 0; mt < 2; ++mt)
#pragma unroll
                for (int nb = 0; nb < 2; ++nb) {
                    int r = r0 + mt * 16, c = c0 + nb * 8;
                    *(float2*)&es[r * 128 + c] =
                        make_float2(acc[mt][nb][0] + acc2[mt][nb][0] * s,
                                    acc[mt][nb][1] + acc2[mt][nb][1] * s);
                    *(float2*)&es[(r + 8) * 128 + c] =
                        make_float2(acc[mt][nb][2] + acc2[mt][nb][2] * s,
                                    acc[mt][nb][3] + acc2[mt][nb][3] * s);
                }
        }
        __syncthreads();

        // ---- epilogue stage 2: gates, state update (fp32 state in regs) ----
        __half* h16_out = h16 + (size_t)bout * (BATCH * DD);
#pragma unroll
        for (int p = 0; p < 4; ++p) {
            int linear = p * 512 + tid;              // 0..2047
            int m = linear >> 5;                     // 0..63
            int dloc = linear & 31;                  // 0..31
            float4 v = *(float4*)&es[m * 128 + dloc * 4];
            float4 bb = __ldg((const float4*)(bias + ctan * 128 + dloc * 4));
            float vz = v.x + bb.x;
            float vr = v.y + bb.y;
            float vh = v.z + bb.z;
            float vu = v.w + bb.w;
            float z = 1.0f / (1.0f + __expf(-vz));
            float r = 1.0f / (1.0f + __expf(-vr));
            float hh = tanhf(vh + r * vu);
            int gm = ctam * CTA_M + m;
            int d = ctan * 32 + dloc;
            float hn = z * hold_reg[p] + (1.0f - z) * hh;
            hold_reg[p] = hn;
            out[(size_t)gm * (TSTEPS * DD) + (size_t)t * DD + d] = hn;
            h16_out[(size_t)gm * DD + d] = __float2half_rn(hn);
        }

        if (have_next) {
            // ---- global barrier: all h16_out visible before A loads ----
            __syncthreads();
            if (tid == 0) {
                __threadfence();
                atomicAdd(&g_bar, 1u);
                const unsigned target = 128u * (unsigned)(t + 1);
                while (*(volatile unsigned*)&g_bar < target) { }
                __threadfence();
            }
            __syncthreads();
            const __half* AgN = h16 + (size_t)bout * (BATCH * DD) + (size_t)ctam * CTA_M * DD;
#pragma unroll
            for (int c = 0; c < 3; ++c) { issue_A(c, c * KC, AgN); cp_commit(); }
        }
    }
#undef KK_BODY
#undef LDSM_A
#undef LDSM_BH
#undef LDSM_BL
}

// ---------------- pack / init kernels ---------------------------------------
__global__ void pack_weights(const float* __restrict__ W, const float* __restrict__ U,
                             const float* __restrict__ b,
                             __half* __restrict__ Wmh, __half* __restrict__ Wml,
                             __half* __restrict__ W1h, __half* __restrict__ W1l,
                             float* __restrict__ bp)
{
    int idx = blockIdx.x * blockDim.x + threadIdx.x;
    if (idx >= NPACK * DD) return;
    int c = idx >> 10;          // packed column (d*4 + gate)
    int k = idx & 1023;
    int d = c >> 2, g = c & 3;
    const int TD = 3 * DD;
    float vm, v1;
    if (g == 0)      { float u = U[(size_t)k * TD + d];            vm = W[(size_t)k * TD + d] + u;            v1 = u; }
    else if (g == 1) { float u = U[(size_t)k * TD + DD + d];       vm = W[(size_t)k * TD + DD + d] + u;       v1 = u; }
    else if (g == 2) { vm = W[(size_t)k * TD + 2 * DD + d];        v1 = 0.0f; }
    else             { float u = U[(size_t)k * TD + 2 * DD + d];   vm = u;    v1 = u; }
    __half h1 = __float2half_rn(vm);
    Wmh[idx] = h1;
    Wml[idx] = __float2half_rn((vm - __half2float(h1)) * 2048.0f);
    __half h2 = __float2half_rn(v1);
    W1h[idx] = h2;
    W1l[idx] = __float2half_rn((v1 - __half2float(h2)) * 2048.0f);
    if (k == 0)
        bp[c] = (g == 0) ? b[d] : (g == 1) ? b[DD + d] : (g == 2) ? b[2 * DD + d] : 0.0f;
}

__global__ void init_h(const float* __restrict__ x, __half* __restrict__ h16)
{
    int i = blockIdx.x * blockDim.x + threadIdx.x;
    if (i == 0) g_bar = 0u;     // reset grid barrier every launch (graph replays)
    if (i < BATCH * DD) h16[i] = __float2half_rn(x[i]);
}

// ---------------- launch -----------------------------------------------------
extern "C" void kernel_launch(void* const* d_in, const int* in_sizes, int n_in,
                              void* d_out, int out_size)
{
    const float* x = (const float*)d_in[0];
    const float* W = (const float*)d_in[1];
    const float* U = (const float*)d_in[2];
    const float* b = (const float*)d_in[3];
    float* out = (float*)d_out;

    void *pWmh, *pWml, *pW1h, *pW1l, *pH16, *pBias;
    cudaGetSymbolAddress(&pWmh, g_Wmh);
    cudaGetSymbolAddress(&pWml, g_Wml);
    cudaGetSymbolAddress(&pW1h, g_W1h);
    cudaGetSymbolAddress(&pW1l, g_W1l);
    cudaGetSymbolAddress(&pH16, g_h16);
    cudaGetSymbolAddress(&pBias, g_bias);
    __half* Wmh = (__half*)pWmh;
    __half* Wml = (__half*)pWml;
    __half* W1h = (__half*)pW1h;
    __half* W1l = (__half*)pW1l;
    __half* H16 = (__half*)pH16;     // [2][BATCH*DD]
    float* Bias = (float*)pBias;

    cudaFuncSetAttribute(gru_persistent_kernel,
                         cudaFuncAttributeMaxDynamicSharedMemorySize, SMEM_DYN);

    pack_weights<<<(NPACK * DD + 255) / 256, 256>>>(W, U, b, Wmh, Wml, W1h, W1l, Bias);
    init_h<<<(BATCH * DD + 255) / 256, 256>>>(x, H16);

    dim3 grid(32, 4);   // 128 CTAs <= 148 SMs, 1 CTA/SM: all co-resident
    gru_persistent_kernel<<<grid, 512, SMEM_DYN>>>(
        Wmh, Wml, W1h, W1l, H16, x, Bias, out);
    (void)in_sizes; (void)n_in; (void)out_size;
}

// round 17
// speedup vs baseline: 1.0565x; 1.0182x over previous
#include <cuda_runtime.h>
#include <cuda_bf16.h>
#include <cuda_fp16.h>
#include <cstdint>
#include <cstddef>

// ============================================================================
// AutoregressiveGRU on GB300 — sm_103 base target, HMMA mma.sync m16n8k16.
//
// fp16 2-term scheme (full correction every chunk):
//   acc  += fp16(h)*fp16(W) ;  acc2 += fp16(h)*(Wlo*2048)
//   res = acc + acc2/2048
// One fused GEMM [256,1024]x[1024,4096] per step.
//
// R17 vs R16: GATE-INTERLEAVED column permutation. Within each 16-col warp
// block, packed col cc holds (d = wn*4 + ((cc>>1)&3), gate = (cc&1)+2*(cc>>3)),
// so each thread's MMA fragment registers contain the full (z,r,xh,uh) quad
// of one d: epilogue computes gates DIRECTLY from acc regs — no smem
// roundtrip, no extra syncs. Bias in per-d float4 quads, loaded once.
// out[] stores moved after barrier-arrive (off critical path).
// ============================================================================

#define DD 1024
#define BATCH 256
#define TSTEPS 128
#define NPACK 4096

#define CTA_M 64
#define CTA_N 128
#define KC 64            // K per chunk (64 fp16 = 128 B/row)
#define KCH 16           // 1024 / 64
#define STAGES 4
#define A_TILE_B (CTA_M * 128)            // 8192
#define B_TILE_B (CTA_N * 128)            // 16384
#define STAGE_BYTES (A_TILE_B + 2 * B_TILE_B)       // 40960
#define SMEM_DYN (STAGES * STAGE_BYTES)             // 163840

// ---------------- device globals --------------------------------------------
__device__ __half g_Wmh[NPACK * DD];     // main weights hi (gate-interleaved)
__device__ __half g_Wml[NPACK * DD];     // main weights (lo * 2048)
__device__ __half g_W1h[NPACK * DD];     // step-1 weights hi
__device__ __half g_W1l[NPACK * DD];     // step-1 weights (lo * 2048)
__device__ __half g_h16[2][BATCH * DD];  // fp16 state ping-pong
__device__ float g_bias[NPACK];          // quad layout: [d*4 + gate]
__device__ unsigned g_bar;               // grid barrier (reset by init_h)

// ---------------- PTX helpers -----------------------------------------------
__device__ __forceinline__ uint32_t smem_u32(const void* p) {
    uint32_t a;
    asm("{ .reg .u64 t; cvta.to.shared.u64 t, %1; cvt.u32.u64 %0, t; }" : "=r"(a) : "l"(p));
    return a;
}
__device__ __forceinline__ void cp16(uint32_t dst, const void* src) {
    asm volatile("cp.async.cg.shared.global [%0], [%1], 16;" :: "r"(dst), "l"(src) : "memory");
}
__device__ __forceinline__ void cp_commit() {
    asm volatile("cp.async.commit_group;" ::: "memory");
}
template <int N>
__device__ __forceinline__ void cp_wait() {
    asm volatile("cp.async.wait_group %0;" :: "n"(N) : "memory");
}
__device__ __forceinline__ void ldsm_x4(uint32_t* r, uint32_t addr) {
    asm volatile("ldmatrix.sync.aligned.m8n8.x4.shared.b16 {%0,%1,%2,%3}, [%4];"
                 : "=r"(r[0]), "=r"(r[1]), "=r"(r[2]), "=r"(r[3]) : "r"(addr));
}
__device__ __forceinline__ void mma_f16(float* c, const uint32_t* a, uint32_t b0, uint32_t b1) {
    asm volatile("mma.sync.aligned.m16n8k16.row.col.f32.f16.f16.f32 "
                 "{%0,%1,%2,%3}, {%4,%5,%6,%7}, {%8,%9}, {%0,%1,%2,%3};"
                 : "+f"(c[0]), "+f"(c[1]), "+f"(c[2]), "+f"(c[3])
                 : "r"(a[0]), "r"(a[1]), "r"(a[2]), "r"(a[3]), "r"(b0), "r"(b1));
}

// ---------------- persistent kernel ------------------------------------------
__global__ __launch_bounds__(512, 1) void gru_persistent_kernel(
    const __half* __restrict__ Wmh, const __half* __restrict__ Wml,
    const __half* __restrict__ W1h, const __half* __restrict__ W1l,
    __half* __restrict__ h16,            // [2][BATCH*DD]
    const float* __restrict__ x,
    const float* __restrict__ bias, float* __restrict__ out)
{
    extern __shared__ __align__(128) char smem_raw[];
    const uint32_t sbase = smem_u32(smem_raw);
    const int tid = threadIdx.x;
    const int wid = tid >> 5, lane = tid & 31;
    const int ctan = blockIdx.x;   // 0..31
    const int ctam = blockIdx.y;   // 0..3

    const int wm = wid & 1;        // 0..1 : 32-row warp block
    const int wn = wid >> 1;       // 0..7 : 16-col warp block

    // per-thread cp.async coords
    const int cprowA = tid >> 3, cpgrpA = tid & 7;
    const uint32_t cpswA = (uint32_t)(cprowA * 128) + (uint32_t)((cpgrpA ^ (cprowA & 7)) << 4);

    auto issue_A = [&](int slot, int k0, const __half* Ag) {
        cp16(sbase + (uint32_t)slot * STAGE_BYTES + cpswA,
             Ag + (size_t)cprowA * DD + k0 + cpgrpA * 8);
    };
    auto issue_Bh = [&](int slot, int k0, const __half* Bhg) {
        uint32_t tb = sbase + (uint32_t)slot * STAGE_BYTES + A_TILE_B;
#pragma unroll
        for (int it = 0; it < 2; ++it) {
            int idx = tid + it * 512;
            int row = idx >> 3, grp = idx & 7;
            uint32_t sw = (uint32_t)(row * 128) + (uint32_t)((grp ^ (row & 7)) << 4);
            cp16(tb + sw, Bhg + (size_t)row * DD + k0 + grp * 8);
        }
    };
    auto issue_Bl = [&](int slot, int k0, const __half* Blg) {
        uint32_t tb = sbase + (uint32_t)slot * STAGE_BYTES + A_TILE_B + B_TILE_B;
#pragma unroll
        for (int it = 0; it < 2; ++it) {
            int idx = tid + it * 512;
            int row = idx >> 3, grp = idx & 7;
            uint32_t sw = (uint32_t)(row * 128) + (uint32_t)((grp ^ (row & 7)) << 4);
            cp16(tb + sw, Blg + (size_t)row * DD + k0 + grp * 8);
        }
    };

    // fragment addressing
    const int arow = wm * 32 + (lane & 15);
    const int agl = (lane >> 4);
    const int brow = wn * 16 + (lane & 7) + ((lane >> 4) & 1) * 8;
    const int bgl = (lane >> 3) & 1;

    uint32_t fa[2][2][4], fbh[2][4], fbl[2][4];

#define LDSM_A(b, mt, kk_) do {                                                      \
    int row_ = arow + (mt) * 16;                                                     \
    uint32_t off_ = (uint32_t)(row_ * 128) +                                         \
                    (uint32_t)(((((kk_) * 2) + agl) ^ (row_ & 7)) << 4);             \
    ldsm_x4(fa[b][mt], aB + off_);                                                   \
} while (0)
#define LDSM_BH(b, kk_) do {                                                         \
    uint32_t off_ = (uint32_t)(brow * 128) +                                         \
                    (uint32_t)(((((kk_) * 2) + bgl) ^ (brow & 7)) << 4);             \
    ldsm_x4(fbh[b], bhB + off_);                                                     \
} while (0)
#define LDSM_BL(b, kk_) do {                                                         \
    uint32_t off_ = (uint32_t)(brow * 128) +                                         \
                    (uint32_t)(((((kk_) * 2) + bgl) ^ (brow & 7)) << 4);             \
    ldsm_x4(fbl[b], blB + off_);                                                     \
} while (0)
#define KK_BODY(bc, bn, kkn, do_ld) do {                                             \
    if (do_ld) LDSM_A(bn, 0, kkn);                                                   \
    mma_f16(acc[0][0],  fa[bc][0], fbh[bc][0], fbh[bc][1]);                          \
    mma_f16(acc[0][1],  fa[bc][0], fbh[bc][2], fbh[bc][3]);                          \
    if (do_ld) LDSM_BH(bn, kkn);                                                     \
    mma_f16(acc2[0][0], fa[bc][0], fbl[bc][0], fbl[bc][1]);                          \
    mma_f16(acc2[0][1], fa[bc][0], fbl[bc][2], fbl[bc][3]);                          \
    if (do_ld) LDSM_A(bn, 1, kkn);                                                   \
    mma_f16(acc[1][0],  fa[bc][1], fbh[bc][0], fbh[bc][1]);                          \
    mma_f16(acc[1][1],  fa[bc][1], fbh[bc][2], fbh[bc][3]);                          \
    if (do_ld) LDSM_BL(bn, kkn);                                                     \
    mma_f16(acc2[1][0], fa[bc][1], fbl[bc][0], fbl[bc][1]);                          \
    mma_f16(acc2[1][1], fa[bc][1], fbl[bc][2], fbl[bc][3]);                          \
} while (0)

    // ---- per-thread output coordinates (gate-interleaved mapping) ----
    // thread owns d = ctan*32 + wn*4 + (lane&3), rows r(mt,rr) = base + mt*16 + rr*8
    const int dglob = ctan * 32 + wn * 4 + (lane & 3);
    const int rowbase = ctam * CTA_M + wm * 32 + (lane >> 2);

    // bias quad (step-invariant): bz,br,bh,(0)
    const float4 bq = __ldg((const float4*)(bias + dglob * 4));

    // fp32 state in registers: p = mt*2 + rr
    float hold_reg[4];
#pragma unroll
    for (int mt = 0; mt < 2; ++mt)
#pragma unroll
        for (int rr = 0; rr < 2; ++rr)
            hold_reg[mt * 2 + rr] = x[(size_t)(rowbase + mt * 16 + rr * 8) * DD + dglob];

    // ---- one-time prologue (t=0): B chunks 0..2 (W1), then A chunks 0..2 ----
    {
        const __half* Bhg0 = W1h + (size_t)ctan * CTA_N * DD;
        const __half* Blg0 = W1l + (size_t)ctan * CTA_N * DD;
        const __half* Ag0 = h16 + (size_t)ctam * CTA_M * DD;   // buffer 0
#pragma unroll
        for (int c = 0; c < 3; ++c) {
            issue_Bh(c, c * KC, Bhg0); issue_Bl(c, c * KC, Blg0); cp_commit();
        }
#pragma unroll
        for (int c = 0; c < 3; ++c) { issue_A(c, c * KC, Ag0); cp_commit(); }
    }

    const __half* BhgN = Wmh + (size_t)ctan * CTA_N * DD;   // steps >= 1
    const __half* BlgN = Wml + (size_t)ctan * CTA_N * DD;

    for (int t = 0; t < TSTEPS; ++t) {
        const int bin = t & 1, bout = bin ^ 1;
        const __half* Ag = h16 + (size_t)bin * (BATCH * DD) + (size_t)ctam * CTA_M * DD;
        const __half* Bhg = (t == 0) ? (W1h + (size_t)ctan * CTA_N * DD) : BhgN;
        const __half* Blg = (t == 0) ? (W1l + (size_t)ctan * CTA_N * DD) : BlgN;
        const bool have_next = (t + 1 < TSTEPS);

        float acc[2][2][4], acc2[2][2][4];
#pragma unroll
        for (int i = 0; i < 2; ++i)
#pragma unroll
            for (int j = 0; j < 2; ++j)
#pragma unroll
                for (int k = 0; k < 4; ++k) { acc[i][j][k] = 0.0f; acc2[i][j][k] = 0.0f; }

        for (int i = 0; i < KCH; ++i) {
            cp_wait<2>();
            __syncthreads();
            uint32_t base = sbase + (uint32_t)(i & (STAGES - 1)) * STAGE_BYTES;
            const uint32_t aB = base;
            const uint32_t bhB = base + A_TILE_B, blB = bhB + B_TILE_B;

            const int pf = i + 3;
            // mode 0: this step's chunk pf; mode 1: next step's B tile; mode 2: none
            int mode, pslot, pk0;
            if (pf < KCH) { mode = 0; pslot = pf & (STAGES - 1); pk0 = pf * KC; }
            else if (have_next && pf - KCH < 3) { mode = 1; pslot = pf - KCH; pk0 = (pf - KCH) * KC; }
            else { mode = 2; pslot = 0; pk0 = 0; }

            LDSM_A(0, 0, 0); LDSM_BH(0, 0); LDSM_A(0, 1, 0); LDSM_BL(0, 0);

            KK_BODY(0, 1, 1, true);
            if (mode == 0) issue_A(pslot, pk0, Ag);
            else if (mode == 1) issue_Bh(pslot, pk0, BhgN);
            KK_BODY(1, 0, 2, true);
            if (mode == 0) issue_Bh(pslot, pk0, Bhg);
            else if (mode == 1) issue_Bl(pslot, pk0, BlgN);
            KK_BODY(0, 1, 3, true);
            if (mode == 0) issue_Bl(pslot, pk0, Blg);
            cp_commit();
            KK_BODY(1, 0, 0, false);
        }

        // ---- epilogue: gates directly from acc registers (no smem roundtrip) ----
        const float s = 1.0f / 2048.0f;
        __half* h16_out = h16 + (size_t)bout * (BATCH * DD);
        float hn_loc[4];
#pragma unroll
        for (int mt = 0; mt < 2; ++mt)
#pragma unroll
            for (int rr = 0; rr < 2; ++rr) {
                const int p = mt * 2 + rr;
                float vz = acc[mt][0][rr * 2 + 0] + acc2[mt][0][rr * 2 + 0] * s + bq.x;
                float vr = acc[mt][0][rr * 2 + 1] + acc2[mt][0][rr * 2 + 1] * s + bq.y;
                float vh = acc[mt][1][rr * 2 + 0] + acc2[mt][1][rr * 2 + 0] * s + bq.z;
                float vu = acc[mt][1][rr * 2 + 1] + acc2[mt][1][rr * 2 + 1] * s;
                float z = 1.0f / (1.0f + __expf(-vz));
                float r = 1.0f / (1.0f + __expf(-vr));
                float hh = tanhf(vh + r * vu);
                float hn = z * hold_reg[p] + (1.0f - z) * hh;
                hold_reg[p] = hn;
                hn_loc[p] = hn;
                h16_out[(size_t)(rowbase + mt * 16 + rr * 8) * DD + dglob] = __float2half_rn(hn);
            }
        __syncthreads();                 // all h16 stores issued

        // arrive early; out[] stores overlap with peers' arrivals
        if (have_next && tid == 0) { __threadfence(); atomicAdd(&g_bar, 1u); }
#pragma unroll
        for (int mt = 0; mt < 2; ++mt)
#pragma unroll
            for (int rr = 0; rr < 2; ++rr)
                out[(size_t)(rowbase + mt * 16 + rr * 8) * (TSTEPS * DD)
                    + (size_t)t * DD + dglob] = hn_loc[mt * 2 + rr];

        if (have_next) {
            if (tid == 0) {
                const unsigned target = 128u * (unsigned)(t + 1);
                while (*(volatile unsigned*)&g_bar < target) { }
                __threadfence();
            }
            __syncthreads();
            const __half* AgN = h16 + (size_t)bout * (BATCH * DD) + (size_t)ctam * CTA_M * DD;
#pragma unroll
            for (int c = 0; c < 3; ++c) { issue_A(c, c * KC, AgN); cp_commit(); }
        }
    }
#undef KK_BODY
#undef LDSM_A
#undef LDSM_BH
#undef LDSM_BL
}

// ---------------- pack / init kernels ---------------------------------------
// Gate-interleaved packed column c: co=c&127, wnb=co>>4, cc=co&15,
// d = (c>>7)*32 + wnb*4 + ((cc>>1)&3), gate = (cc&1) + 2*(cc>>3).
__global__ void pack_weights(const float* __restrict__ W, const float* __restrict__ U,
                             const float* __restrict__ b,
                             __half* __restrict__ Wmh, __half* __restrict__ Wml,
                             __half* __restrict__ W1h, __half* __restrict__ W1l,
                             float* __restrict__ bp)
{
    int idx = blockIdx.x * blockDim.x + threadIdx.x;
    if (idx >= NPACK * DD) return;
    int c = idx >> 10;
    int k = idx & 1023;
    int co = c & 127;
    int wnb = co >> 4, cc = co & 15;
    int dl = (cc >> 1) & 3;
    int g = (cc & 1) + ((cc >> 3) << 1);
    int d = (c >> 7) * 32 + wnb * 4 + dl;
    const int TD = 3 * DD;
    float vm, v1;
    if (g == 0)      { float u = U[(size_t)k * TD + d];            vm = W[(size_t)k * TD + d] + u;            v1 = u; }
    else if (g == 1) { float u = U[(size_t)k * TD + DD + d];       vm = W[(size_t)k * TD + DD + d] + u;       v1 = u; }
    else if (g == 2) { vm = W[(size_t)k * TD + 2 * DD + d];        v1 = 0.0f; }
    else             { float u = U[(size_t)k * TD + 2 * DD + d];   vm = u;    v1 = u; }
    __half h1 = __float2half_rn(vm);
    Wmh[idx] = h1;
    Wml[idx] = __float2half_rn((vm - __half2float(h1)) * 2048.0f);
    __half h2 = __float2half_rn(v1);
    W1h[idx] = h2;
    W1l[idx] = __float2half_rn((v1 - __half2float(h2)) * 2048.0f);
    if (k == 0)
        bp[d * 4 + g] = (g == 0) ? b[d] : (g == 1) ? b[DD + d] : (g == 2) ? b[2 * DD + d] : 0.0f;
}

__global__ void init_h(const float* __restrict__ x, __half* __restrict__ h16)
{
    int i = blockIdx.x * blockDim.x + threadIdx.x;
    if (i == 0) g_bar = 0u;     // reset grid barrier every launch (graph replays)
    if (i < BATCH * DD) h16[i] = __float2half_rn(x[i]);
}

// ---------------- launch -----------------------------------------------------
extern "C" void kernel_launch(void* const* d_in, const int* in_sizes, int n_in,
                              void* d_out, int out_size)
{
    const float* x = (const float*)d_in[0];
    const float* W = (const float*)d_in[1];
    const float* U = (const float*)d_in[2];
    const float* b = (const float*)d_in[3];
    float* out = (float*)d_out;

    void *pWmh, *pWml, *pW1h, *pW1l, *pH16, *pBias;
    cudaGetSymbolAddress(&pWmh, g_Wmh);
    cudaGetSymbolAddress(&pWml, g_Wml);
    cudaGetSymbolAddress(&pW1h, g_W1h);
    cudaGetSymbolAddress(&pW1l, g_W1l);
    cudaGetSymbolAddress(&pH16, g_h16);
    cudaGetSymbolAddress(&pBias, g_bias);
    __half* Wmh = (__half*)pWmh;
    __half* Wml = (__half*)pWml;
    __half* W1h = (__half*)pW1h;
    __half* W1l = (__half*)pW1l;
    __half* H16 = (__half*)pH16;     // [2][BATCH*DD]
    float* Bias = (float*)pBias;

    cudaFuncSetAttribute(gru_persistent_kernel,
                         cudaFuncAttributeMaxDynamicSharedMemorySize, SMEM_DYN);

    pack_weights<<<(NPACK * DD + 255) / 256, 256>>>(W, U, b, Wmh, Wml, W1h, W1l, Bias);
    init_h<<<(BATCH * DD + 255) / 256, 256>>>(x, H16);

    dim3 grid(32, 4);   // 128 CTAs <= 148 SMs, 1 CTA/SM: all co-resident
    gru_persistent_kernel<<<grid, 512, SMEM_DYN>>>(
        Wmh, Wml, W1h, W1l, H16, x, Bias, out);
    (void)in_sizes; (void)n_in; (void)out_size;
}